// round 3
// baseline (speedup 1.0000x reference)
#include <cuda_runtime.h>

// ---------------- scratch ----------------
__device__ float g_ta[8*256*64];        // [n][p][i]
__device__ float g_tb[8*256*64];        // [n][p][j]
__device__ float g_tc[256*512];         // [p][(n,k)]
__device__ float g_td[8*256*64];        // [n][p][h]
__device__ float g_te[8*256*64];        // [n][q][g]
__device__ float g_tbsT[64*256];        // [j][q]
__device__ float g_WKt[512*4096];       // [(n,k)][(i,j)]
__device__ float g_step1[256*4096];     // [r][(i,j)]
__device__ float g_step2[256*64*256];   // [r][i][q]
__device__ float g_M[8*256*4096];       // [n][r][(h,g)]
__device__ float g_zint[256*512];       // [r][(n,f)]

// ---------------- W_K transpose: WKt[(n,k)][(i,j)] = W_K[n][i][j][k] ----------------
__global__ void wkt_kernel(const float* __restrict__ WK) {
    int o = blockIdx.x * 256 + threadIdx.x;   // 2,097,152 elements
    int n = o >> 18, k = (o >> 12) & 63, ij = o & 4095;
    int i = ij >> 6, j = ij & 63;
    g_WKt[o] = WK[(((n*64 + i)*64 + j) << 6) + k];
}

// ---------------- tbsT[j][q] = sum_n tb[n][q][j] ----------------
__global__ void tbs_kernel() {
    int t = blockIdx.x * 256 + threadIdx.x;   // 16384
    int j = t >> 8, q = t & 255;
    float s = 0.f;
#pragma unroll
    for (int n = 0; n < 8; n++) s += g_tb[n*16384 + q*64 + j];
    g_tbsT[j*256 + q] = s;
}

// ---------------- generic SGEMM: C = A[M,K]*B[K,N] (+bias[col]) ----------------
// 64x64 tile, KT=16, 256 threads, 4x4 per thread. M,N %64==0, K %16==0.
__global__ void __launch_bounds__(256) sgemm_kernel(
    const float* __restrict__ A, const float* __restrict__ B,
    float* __restrict__ C, const float* __restrict__ bias,
    int K, int lda, int ldb, int ldc,
    long long sA, long long sB, long long sC, long long sBias)
{
    __shared__ float As[16*65];   // [k][m] padded
    __shared__ float Bs[16*64];   // [k][n]
    A += (long long)blockIdx.z * sA;
    B += (long long)blockIdx.z * sB;
    C += (long long)blockIdx.z * sC;
    if (bias) bias += (long long)blockIdx.z * sBias;
    const int bm = blockIdx.y * 64, bn = blockIdx.x * 64;
    const int tid = threadIdx.x, tx = tid & 15, ty = tid >> 4;
    float acc[4][4] = {};
    for (int k0 = 0; k0 < K; k0 += 16) {
        __syncthreads();
#pragma unroll
        for (int t = tid; t < 1024; t += 256) {
            int m = t >> 4, kk = t & 15;                    // consecutive tid -> consecutive kk
            As[kk*65 + m] = A[(bm + m)*lda + k0 + kk];
        }
#pragma unroll
        for (int t = tid; t < 1024; t += 256) {
            int kk = t >> 6, nn = t & 63;                   // fully coalesced
            Bs[kk*64 + nn] = B[(long long)(k0 + kk)*ldb + bn + nn];
        }
        __syncthreads();
#pragma unroll
        for (int kk = 0; kk < 16; kk++) {
            float4 b4 = *(const float4*)&Bs[kk*64 + tx*4];
#pragma unroll
            for (int ii = 0; ii < 4; ii++) {
                float a = As[kk*65 + ty*4 + ii];
                acc[ii][0] += a * b4.x; acc[ii][1] += a * b4.y;
                acc[ii][2] += a * b4.z; acc[ii][3] += a * b4.w;
            }
        }
    }
#pragma unroll
    for (int ii = 0; ii < 4; ii++) {
        float4 v = make_float4(acc[ii][0], acc[ii][1], acc[ii][2], acc[ii][3]);
        if (bias) {
            v.x += bias[bn + tx*4 + 0]; v.y += bias[bn + tx*4 + 1];
            v.z += bias[bn + tx*4 + 2]; v.w += bias[bn + tx*4 + 3];
        }
        *(float4*)&C[(long long)(bm + ty*4 + ii)*ldc + bn + tx*4] = v;
    }
}

// ---------------- fused attention: per (n,r) block ----------------
// M[h,g] = sum_{q<r} te[q,g] * ( sum_{p<q} exp(s[p,q]/64) * td[p,h] ),
// s[p,q] = sum_i ta[p,i]*step2[r,i,q]. Output g_M = M/denom.
__global__ void __launch_bounds__(256) attn_kernel() {
    __shared__ float bufA[4096];   // ta tile -> e tile [p][q]
    __shared__ float bufB[4096];   // step2 tile [i][q] -> w [q][h]
    __shared__ float bufC[4096];   // td tile [p][h] -> te [q][g]
    const int idx = blockIdx.x;
    const int n = idx & 7;
    const int r = 255 - (idx >> 3);            // big-work blocks first
    const int tid = threadIdx.x, tx = tid & 15, ty = tid >> 4;
    float* Mout = g_M + (long long)(n*256 + r) * 4096;

    if (r < 2) {                                // empty valid set -> z = 0
        float4 z4 = make_float4(0.f, 0.f, 0.f, 0.f);
#pragma unroll
        for (int ii = 0; ii < 4; ii++)
            *(float4*)&Mout[(ty*4 + ii)*64 + tx*4] = z4;
        return;
    }
    const float* ta  = g_ta + n*16384;
    const float* td  = g_td + n*16384;
    const float* te  = g_te + n*16384;
    const float* st2 = g_step2 + r*16384;

    float Mreg[4][4] = {};
    float dsum = 0.f;

    for (int q0 = 0; q0 < r; q0 += 64) {
        __syncthreads();                        // bufB/bufC free from prev q-tile
        for (int t = tid; t < 4096; t += 256)   // step2 tile [i][q0+q]
            bufB[t] = st2[(t >> 6)*256 + q0 + (t & 63)];
        float wreg[4][4] = {};

        for (int p0 = 0; p0 <= q0; p0 += 64) {
            __syncthreads();                    // also covers bufB load on first iter
            for (int t = tid; t < 4096; t += 256) {
                int row = t >> 6, col = t & 63;
                bufA[t] = ta[(p0 + row)*64 + col];
                bufC[t] = td[(p0 + row)*64 + col];
            }
            __syncthreads();
            // score GEMM: s[p][q] = sum_i ta[p][i]*st2[i][q]
            float sreg[4][4] = {};
#pragma unroll 8
            for (int kk = 0; kk < 64; kk++) {
                float4 b4 = *(const float4*)&bufB[kk*64 + tx*4];
#pragma unroll
                for (int ii = 0; ii < 4; ii++) {
                    float a = bufA[(ty*4 + ii)*64 + kk];
                    sreg[ii][0] += a * b4.x; sreg[ii][1] += a * b4.y;
                    sreg[ii][2] += a * b4.z; sreg[ii][3] += a * b4.w;
                }
            }
            __syncthreads();                    // done reading bufA
            // exp + causal mask (p<q<r) -> e tile into bufA
#pragma unroll
            for (int ii = 0; ii < 4; ii++) {
                int p = p0 + ty*4 + ii;
                float4 e4;
                float* ep = &e4.x;
#pragma unroll
                for (int jj = 0; jj < 4; jj++) {
                    int q = q0 + tx*4 + jj;
                    float v = (p < q && q < r) ? __expf(sreg[ii][jj] * 0.015625f) : 0.f;
                    ep[jj] = v;
                    dsum += v;
                }
                *(float4*)&bufA[(ty*4 + ii)*64 + tx*4] = e4;
            }
            __syncthreads();
            // w GEMM: w[q][h] += e[p][q]*td[p][h]
#pragma unroll 8
            for (int kk = 0; kk < 64; kk++) {
                float4 t4 = *(const float4*)&bufC[kk*64 + tx*4];
#pragma unroll
                for (int ii = 0; ii < 4; ii++) {
                    float e = bufA[kk*64 + ty*4 + ii];
                    wreg[ii][0] += e * t4.x; wreg[ii][1] += e * t4.y;
                    wreg[ii][2] += e * t4.z; wreg[ii][3] += e * t4.w;
                }
            }
        }
        __syncthreads();                        // st2/td dead -> reuse buffers
#pragma unroll
        for (int ii = 0; ii < 4; ii++)          // w -> bufB as [q][h]
            *(float4*)&bufB[(ty*4 + ii)*64 + tx*4] =
                make_float4(wreg[ii][0], wreg[ii][1], wreg[ii][2], wreg[ii][3]);
        for (int t = tid; t < 4096; t += 256)   // te tile [q][g] -> bufC
            bufC[t] = te[(q0 + (t >> 6))*64 + (t & 63)];
        __syncthreads();
        // M GEMM: M[h][g] += w[q][h]*te[q][g]
#pragma unroll 8
        for (int kk = 0; kk < 64; kk++) {
            float4 t4 = *(const float4*)&bufC[kk*64 + tx*4];
#pragma unroll
            for (int ii = 0; ii < 4; ii++) {
                float w = bufB[kk*64 + ty*4 + ii];
                Mreg[ii][0] += w * t4.x; Mreg[ii][1] += w * t4.y;
                Mreg[ii][2] += w * t4.z; Mreg[ii][3] += w * t4.w;
            }
        }
    }
    // block-reduce denom, normalize, store
    __syncthreads();
    bufA[tid] = dsum;
    __syncthreads();
#pragma unroll
    for (int s = 128; s > 0; s >>= 1) {
        if (tid < s) bufA[tid] += bufA[tid + s];
        __syncthreads();
    }
    float inv = 1.0f / bufA[0];
#pragma unroll
    for (int ii = 0; ii < 4; ii++)
        *(float4*)&Mout[(ty*4 + ii)*64 + tx*4] =
            make_float4(Mreg[ii][0]*inv, Mreg[ii][1]*inv, Mreg[ii][2]*inv, Mreg[ii][3]*inv);
}

// ---------------- host ----------------
static float* sym(const void* s) {
    void* p = nullptr;
    cudaGetSymbolAddress(&p, s);
    return (float*)p;
}

extern "C" void kernel_launch(void* const* d_in, const int* in_sizes, int n_in,
                              void* d_out, int out_size) {
    (void)in_sizes; (void)n_in; (void)out_size;
    const float* x  = (const float*)d_in[0];
    const float* WA = (const float*)d_in[1];  const float* bA = (const float*)d_in[2];
    const float* WB = (const float*)d_in[3];  const float* bB = (const float*)d_in[4];
    const float* WC = (const float*)d_in[5];  const float* bC = (const float*)d_in[6];
    const float* WD = (const float*)d_in[7];  const float* bD = (const float*)d_in[8];
    const float* WE = (const float*)d_in[9];  const float* bE = (const float*)d_in[10];
    const float* WV = (const float*)d_in[11];
    const float* WK = (const float*)d_in[12];
    const float* WO = (const float*)d_in[13];
    const float* bO = (const float*)d_in[14];
    float* out = (float*)d_out;

    float* ta   = sym(g_ta);    float* tb   = sym(g_tb);
    float* tc   = sym(g_tc);    float* td   = sym(g_td);
    float* te   = sym(g_te);    float* tbsT = sym(g_tbsT);
    float* WKt  = sym(g_WKt);   float* s1   = sym(g_step1);
    float* s2   = sym(g_step2); float* Mb   = sym(g_M);
    float* zint = sym(g_zint);

    // W_K transpose
    wkt_kernel<<<8192, 256>>>(WK);

    // projections: t_s[n][p][h] = x @ W_s[n] + b_s[n]   (batched over n)
    dim3 gp(1, 4, 8);
    sgemm_kernel<<<gp, 256>>>(x, WA, ta, bA, 512, 512, 64, 64,  0, 32768, 16384, 64);
    sgemm_kernel<<<gp, 256>>>(x, WB, tb, bB, 512, 512, 64, 64,  0, 32768, 16384, 64);
    sgemm_kernel<<<gp, 256>>>(x, WC, tc, bC, 512, 512, 64, 512, 0, 32768, 64,    64); // [p][(n,k)]
    sgemm_kernel<<<gp, 256>>>(x, WD, td, bD, 512, 512, 64, 64,  0, 32768, 16384, 64);
    sgemm_kernel<<<gp, 256>>>(x, WE, te, bE, 512, 512, 64, 64,  0, 32768, 16384, 64);

    // tb summed over n, transposed
    tbs_kernel<<<64, 256>>>();

    // step1[r][(i,j)] = tc[r][(n,k)] @ WKt[(n,k)][(i,j)]   M=256 N=4096 K=512
    sgemm_kernel<<<dim3(64, 4, 1), 256>>>(tc, WKt, s1, nullptr, 512, 512, 4096, 4096, 0, 0, 0, 0);

    // step2[(r,i)][q] = step1[(r,i)][j] @ tbsT[j][q]       M=16384 N=256 K=64
    sgemm_kernel<<<dim3(4, 256, 1), 256>>>(s1, tbsT, s2, nullptr, 64, 64, 256, 256, 0, 0, 0, 0);

    // fused masked-softmax combine -> g_M[n][r][(h,g)]
    attn_kernel<<<2048, 256>>>();

    // zint[r][(n,f)] = M[n][r][(h,g)] @ WV[n][(h,g)][f]    batched over n
    sgemm_kernel<<<dim3(1, 4, 8), 256>>>(Mb, WV, zint, nullptr, 4096, 4096, 64, 512,
                                         1048576LL, 262144LL, 64LL, 0);

    // out[r][d] = zint[r][(n,f)] @ WO[(n,f)][d] + b_O      M=256 N=512 K=512
    sgemm_kernel<<<dim3(8, 4, 1), 256>>>(zint, WO, out, bO, 512, 512, 512, 512, 0, 0, 0, 0);
}

// round 4
// speedup vs baseline: 1.6816x; 1.6816x over previous
#include <cuda_runtime.h>

// ---------------- scratch ----------------
__device__ float g_ta[8*256*64];        // [n][p][i]
__device__ float g_tb[8*256*64];        // [n][p][j]
__device__ float g_tc[256*512];         // [p][(n,k)]
__device__ float g_td[8*256*64];        // [n][p][h]
__device__ float g_te[8*256*64];        // [n][q][g]
__device__ float g_tbsT[64*256];        // [j][q]
__device__ float g_WKt[512*4096];       // [(n,k)][(i,j)]
__device__ float g_step1[256*4096];     // [r][(i,j)]
__device__ float g_step2[256*64*256];   // [r][i][q]
__device__ float g_M[8*256*4096];       // [n][r][(h,g)]
__device__ float g_zp[8*256*512];       // split-K partials for zint
__device__ float g_zint[256*512];       // [r][(n,f)]

// ---------------- W_K transpose: WKt[(n,k)][(i,j)] = W_K[n][i][j][k] ----------------
__global__ void wkt_kernel(const float* __restrict__ WK) {
    int o = blockIdx.x * 256 + threadIdx.x;   // 2,097,152 elements
    int n = o >> 18, k = (o >> 12) & 63, ij = o & 4095;
    int i = ij >> 6, j = ij & 63;
    g_WKt[o] = WK[(((n*64 + i)*64 + j) << 6) + k];
}

// ---------------- tbsT[j][q] = sum_n tb[n][q][j] ----------------
__global__ void tbs_kernel() {
    int t = blockIdx.x * 256 + threadIdx.x;   // 16384
    int j = t >> 8, q = t & 255;
    float s = 0.f;
#pragma unroll
    for (int n = 0; n < 8; n++) s += g_tb[n*16384 + q*64 + j];
    g_tbsT[j*256 + q] = s;
}

// ---------------- fused projections: all 5 t_s = x @ W_s[n] + b_s[n] ----------------
// grid (1, 4, 40): z = s*8 + n.  64x64 tile, K=512.
__global__ void __launch_bounds__(256) proj_kernel(
    const float* __restrict__ x,
    const float* __restrict__ W0, const float* __restrict__ b0,
    const float* __restrict__ W1, const float* __restrict__ b1,
    const float* __restrict__ W2, const float* __restrict__ b2,
    const float* __restrict__ W3, const float* __restrict__ b3,
    const float* __restrict__ W4, const float* __restrict__ b4)
{
    __shared__ float As[16*65];
    __shared__ float Bs[16*64];
    const int s = blockIdx.z >> 3, n = blockIdx.z & 7;
    const float *W, *b;
    if      (s == 0) { W = W0; b = b0; }
    else if (s == 1) { W = W1; b = b1; }
    else if (s == 2) { W = W2; b = b2; }
    else if (s == 3) { W = W3; b = b3; }
    else             { W = W4; b = b4; }
    W += n * 32768;  b += n * 64;
    const int bm = blockIdx.y * 64;
    const int tid = threadIdx.x, tx = tid & 15, ty = tid >> 4;
    float acc[4][4] = {};
    for (int k0 = 0; k0 < 512; k0 += 16) {
        __syncthreads();
#pragma unroll
        for (int t = tid; t < 1024; t += 256) {
            int m = t >> 4, kk = t & 15;
            As[kk*65 + m] = x[(bm + m)*512 + k0 + kk];
        }
#pragma unroll
        for (int t = tid; t < 1024; t += 256) {
            int kk = t >> 6, nn = t & 63;
            Bs[kk*64 + nn] = W[(k0 + kk)*64 + nn];
        }
        __syncthreads();
#pragma unroll
        for (int kk = 0; kk < 16; kk++) {
            float4 b4v = *(const float4*)&Bs[kk*64 + tx*4];
#pragma unroll
            for (int ii = 0; ii < 4; ii++) {
                float a = As[kk*65 + ty*4 + ii];
                acc[ii][0] += a * b4v.x; acc[ii][1] += a * b4v.y;
                acc[ii][2] += a * b4v.z; acc[ii][3] += a * b4v.w;
            }
        }
    }
    float4 bias4 = *(const float4*)&b[tx*4];
    if (s == 2) {   // tc: [p][(n,k)]
#pragma unroll
        for (int ii = 0; ii < 4; ii++)
            *(float4*)&g_tc[(bm + ty*4 + ii)*512 + n*64 + tx*4] =
                make_float4(acc[ii][0]+bias4.x, acc[ii][1]+bias4.y,
                            acc[ii][2]+bias4.z, acc[ii][3]+bias4.w);
    } else {        // [n][p][h]
        float* dst = (s == 0) ? g_ta : (s == 1) ? g_tb : (s == 3) ? g_td : g_te;
        dst += n*16384;
#pragma unroll
        for (int ii = 0; ii < 4; ii++)
            *(float4*)&dst[(bm + ty*4 + ii)*64 + tx*4] =
                make_float4(acc[ii][0]+bias4.x, acc[ii][1]+bias4.y,
                            acc[ii][2]+bias4.z, acc[ii][3]+bias4.w);
    }
}

// ---------------- generic SGEMM: C = A[M,K]*B[K,N] (+bias[col]) ----------------
__global__ void __launch_bounds__(256) sgemm_kernel(
    const float* __restrict__ A, const float* __restrict__ B,
    float* __restrict__ C, const float* __restrict__ bias,
    int K, int lda, int ldb, int ldc,
    long long sA, long long sB, long long sC)
{
    __shared__ float As[16*65];
    __shared__ float Bs[16*64];
    A += (long long)blockIdx.z * sA;
    B += (long long)blockIdx.z * sB;
    C += (long long)blockIdx.z * sC;
    const int bm = blockIdx.y * 64, bn = blockIdx.x * 64;
    const int tid = threadIdx.x, tx = tid & 15, ty = tid >> 4;
    float acc[4][4] = {};
    for (int k0 = 0; k0 < K; k0 += 16) {
        __syncthreads();
#pragma unroll
        for (int t = tid; t < 1024; t += 256) {
            int m = t >> 4, kk = t & 15;
            As[kk*65 + m] = A[(bm + m)*lda + k0 + kk];
        }
#pragma unroll
        for (int t = tid; t < 1024; t += 256) {
            int kk = t >> 6, nn = t & 63;
            Bs[kk*64 + nn] = B[(long long)(k0 + kk)*ldb + bn + nn];
        }
        __syncthreads();
#pragma unroll
        for (int kk = 0; kk < 16; kk++) {
            float4 b4 = *(const float4*)&Bs[kk*64 + tx*4];
#pragma unroll
            for (int ii = 0; ii < 4; ii++) {
                float a = As[kk*65 + ty*4 + ii];
                acc[ii][0] += a * b4.x; acc[ii][1] += a * b4.y;
                acc[ii][2] += a * b4.z; acc[ii][3] += a * b4.w;
            }
        }
    }
#pragma unroll
    for (int ii = 0; ii < 4; ii++) {
        float4 v = make_float4(acc[ii][0], acc[ii][1], acc[ii][2], acc[ii][3]);
        if (bias) {
            v.x += bias[bn + tx*4 + 0]; v.y += bias[bn + tx*4 + 1];
            v.z += bias[bn + tx*4 + 2]; v.w += bias[bn + tx*4 + 3];
        }
        *(float4*)&C[(long long)(bm + ty*4 + ii)*ldc + bn + tx*4] = v;
    }
}

// ---------------- fused attention: per (n,r) block ----------------
__global__ void __launch_bounds__(256) attn_kernel() {
    __shared__ float bufA[4096];
    __shared__ float bufB[4096];
    __shared__ float bufC[4096];
    const int idx = blockIdx.x;
    const int n = idx & 7;
    const int r = 255 - (idx >> 3);            // big-work blocks first
    const int tid = threadIdx.x, tx = tid & 15, ty = tid >> 4;
    float* Mout = g_M + (long long)(n*256 + r) * 4096;

    if (r < 2) {
        float4 z4 = make_float4(0.f, 0.f, 0.f, 0.f);
#pragma unroll
        for (int ii = 0; ii < 4; ii++)
            *(float4*)&Mout[(ty*4 + ii)*64 + tx*4] = z4;
        return;
    }
    const float* ta  = g_ta + n*16384;
    const float* td  = g_td + n*16384;
    const float* te  = g_te + n*16384;
    const float* st2 = g_step2 + r*16384;

    float Mreg[4][4] = {};
    float dsum = 0.f;

    for (int q0 = 0; q0 < r; q0 += 64) {
        __syncthreads();
        for (int t = tid; t < 4096; t += 256)
            bufB[t] = st2[(t >> 6)*256 + q0 + (t & 63)];
        float wreg[4][4] = {};

        for (int p0 = 0; p0 <= q0; p0 += 64) {
            __syncthreads();
            for (int t = tid; t < 4096; t += 256) {
                int row = t >> 6, col = t & 63;
                bufA[t] = ta[(p0 + row)*64 + col];
                bufC[t] = td[(p0 + row)*64 + col];
            }
            __syncthreads();
            float sreg[4][4] = {};
#pragma unroll 8
            for (int kk = 0; kk < 64; kk++) {
                float4 b4 = *(const float4*)&bufB[kk*64 + tx*4];
#pragma unroll
                for (int ii = 0; ii < 4; ii++) {
                    float a = bufA[(ty*4 + ii)*64 + kk];
                    sreg[ii][0] += a * b4.x; sreg[ii][1] += a * b4.y;
                    sreg[ii][2] += a * b4.z; sreg[ii][3] += a * b4.w;
                }
            }
            __syncthreads();
#pragma unroll
            for (int ii = 0; ii < 4; ii++) {
                int p = p0 + ty*4 + ii;
                float4 e4;
                float* ep = &e4.x;
#pragma unroll
                for (int jj = 0; jj < 4; jj++) {
                    int q = q0 + tx*4 + jj;
                    float v = (p < q && q < r) ? __expf(sreg[ii][jj] * 0.015625f) : 0.f;
                    ep[jj] = v;
                    dsum += v;
                }
                *(float4*)&bufA[(ty*4 + ii)*64 + tx*4] = e4;
            }
            __syncthreads();
#pragma unroll 8
            for (int kk = 0; kk < 64; kk++) {
                float4 t4 = *(const float4*)&bufC[kk*64 + tx*4];
#pragma unroll
                for (int ii = 0; ii < 4; ii++) {
                    float e = bufA[kk*64 + ty*4 + ii];
                    wreg[ii][0] += e * t4.x; wreg[ii][1] += e * t4.y;
                    wreg[ii][2] += e * t4.z; wreg[ii][3] += e * t4.w;
                }
            }
        }
        __syncthreads();
#pragma unroll
        for (int ii = 0; ii < 4; ii++)
            *(float4*)&bufB[(ty*4 + ii)*64 + tx*4] =
                make_float4(wreg[ii][0], wreg[ii][1], wreg[ii][2], wreg[ii][3]);
        for (int t = tid; t < 4096; t += 256)
            bufC[t] = te[(q0 + (t >> 6))*64 + (t & 63)];
        __syncthreads();
#pragma unroll 8
        for (int kk = 0; kk < 64; kk++) {
            float4 t4 = *(const float4*)&bufC[kk*64 + tx*4];
#pragma unroll
            for (int ii = 0; ii < 4; ii++) {
                float w = bufB[kk*64 + ty*4 + ii];
                Mreg[ii][0] += w * t4.x; Mreg[ii][1] += w * t4.y;
                Mreg[ii][2] += w * t4.z; Mreg[ii][3] += w * t4.w;
            }
        }
    }
    __syncthreads();
    bufA[tid] = dsum;
    __syncthreads();
#pragma unroll
    for (int s = 128; s > 0; s >>= 1) {
        if (tid < s) bufA[tid] += bufA[tid + s];
        __syncthreads();
    }
    float inv = 1.0f / bufA[0];
#pragma unroll
    for (int ii = 0; ii < 4; ii++)
        *(float4*)&Mout[(ty*4 + ii)*64 + tx*4] =
            make_float4(Mreg[ii][0]*inv, Mreg[ii][1]*inv, Mreg[ii][2]*inv, Mreg[ii][3]*inv);
}

// ---------------- zint split-K: partial[kc][r][(n,f)] = M[n][r, kc-chunk] @ WV[n][kc-chunk] ----------------
// grid (8 kc, 4 mtile, 8 n), K-chunk = 512
__global__ void __launch_bounds__(256) zint_kernel(const float* __restrict__ WV) {
    __shared__ float As[16*65];
    __shared__ float Bs[16*64];
    const int kc = blockIdx.x, n = blockIdx.z;
    const int bm = blockIdx.y * 64;
    const float* A = g_M + (long long)n*1048576 + (long long)kc*512;
    const float* B = WV + (long long)n*262144 + (long long)kc*512*64;
    float* C = g_zp + (long long)kc*131072;
    const int tid = threadIdx.x, tx = tid & 15, ty = tid >> 4;
    float acc[4][4] = {};
    for (int k0 = 0; k0 < 512; k0 += 16) {
        __syncthreads();
#pragma unroll
        for (int t = tid; t < 1024; t += 256) {
            int m = t >> 4, kk = t & 15;
            As[kk*65 + m] = A[(long long)(bm + m)*4096 + k0 + kk];
        }
#pragma unroll
        for (int t = tid; t < 1024; t += 256) {
            int kk = t >> 6, nn = t & 63;
            Bs[kk*64 + nn] = B[(k0 + kk)*64 + nn];
        }
        __syncthreads();
#pragma unroll
        for (int kk = 0; kk < 16; kk++) {
            float4 b4 = *(const float4*)&Bs[kk*64 + tx*4];
#pragma unroll
            for (int ii = 0; ii < 4; ii++) {
                float a = As[kk*65 + ty*4 + ii];
                acc[ii][0] += a * b4.x; acc[ii][1] += a * b4.y;
                acc[ii][2] += a * b4.z; acc[ii][3] += a * b4.w;
            }
        }
    }
#pragma unroll
    for (int ii = 0; ii < 4; ii++)
        *(float4*)&C[(bm + ty*4 + ii)*512 + n*64 + tx*4] =
            make_float4(acc[ii][0], acc[ii][1], acc[ii][2], acc[ii][3]);
}

__global__ void zred_kernel() {
    int t = blockIdx.x * 256 + threadIdx.x;   // 131072
    float s = 0.f;
#pragma unroll
    for (int kc = 0; kc < 8; kc++) s += g_zp[kc*131072 + t];
    g_zint[t] = s;
}

// ---------------- host ----------------
static float* sym(const void* s) {
    void* p = nullptr;
    cudaGetSymbolAddress(&p, s);
    return (float*)p;
}

extern "C" void kernel_launch(void* const* d_in, const int* in_sizes, int n_in,
                              void* d_out, int out_size) {
    (void)in_sizes; (void)n_in; (void)out_size;
    const float* x  = (const float*)d_in[0];
    const float* WA = (const float*)d_in[1];  const float* bA = (const float*)d_in[2];
    const float* WB = (const float*)d_in[3];  const float* bB = (const float*)d_in[4];
    const float* WC = (const float*)d_in[5];  const float* bC = (const float*)d_in[6];
    const float* WD = (const float*)d_in[7];  const float* bD = (const float*)d_in[8];
    const float* WE = (const float*)d_in[9];  const float* bE = (const float*)d_in[10];
    const float* WV = (const float*)d_in[11];
    const float* WK = (const float*)d_in[12];
    const float* WO = (const float*)d_in[13];
    const float* bO = (const float*)d_in[14];
    float* out = (float*)d_out;

    float* tc   = sym(g_tc);    float* tbsT = sym(g_tbsT);
    float* WKt  = sym(g_WKt);   float* s1   = sym(g_step1);
    float* s2   = sym(g_step2); float* zint = sym(g_zint);

    // 1: W_K transpose
    wkt_kernel<<<8192, 256>>>(WK);
    // 2: all projections fused
    proj_kernel<<<dim3(1, 4, 40), 256>>>(x, WA, bA, WB, bB, WC, bC, WD, bD, WE, bE);
    // 3: tb summed over n, transposed
    tbs_kernel<<<64, 256>>>();
    // 4: step1[r][(i,j)] = tc @ WKt      M=256 N=4096 K=512
    sgemm_kernel<<<dim3(64, 4, 1), 256>>>(tc, WKt, s1, nullptr, 512, 512, 4096, 4096, 0, 0, 0);
    // 5: step2[(r,i)][q] = step1 @ tbsT  M=16384 N=256 K=64
    sgemm_kernel<<<dim3(4, 256, 1), 256>>>(s1, tbsT, s2, nullptr, 64, 64, 256, 256, 0, 0, 0);
    // 6: fused masked-softmax combine -> g_M   (this is the profiled launch)
    attn_kernel<<<2048, 256>>>();
    // 7: zint split-K partials
    zint_kernel<<<dim3(8, 4, 8), 256>>>(WV);
    // 8: reduce partials
    zred_kernel<<<512, 256>>>();
    // 9: out = zint @ WO + b_O           M=256 N=512 K=512
    sgemm_kernel<<<dim3(8, 4, 1), 256>>>(zint, WO, out, bO, 512, 512, 512, 512, 0, 0, 0);
}